// round 3
// baseline (speedup 1.0000x reference)
#include <cuda_runtime.h>
#include <math.h>

// ---------------------------------------------------------------------------
// Problem constants
//   x: [2, 2048, 1024]  W_q/W_k/W_v: [1024,1024]  W_out: [1024,1024] b_out:[1024]
//   16 heads x 64 dim, causal, softmax scale 1/8, fp32 everywhere.
// ---------------------------------------------------------------------------
#define BATCH   2
#define SEQ     2048
#define DMODEL  1024
#define NHEAD   16
#define HDIM    64
#define MTOT    (BATCH * SEQ)          // 4096 rows

// Scratch (device globals: no allocations allowed in kernel_launch)
__device__ float g_q[MTOT * DMODEL];
__device__ float g_k[MTOT * DMODEL];
__device__ float g_v[MTOT * DMODEL];
__device__ float g_ctx[MTOT * DMODEL];

// ---------------------------------------------------------------------------
// SGEMM: C[M,N] = A[M,K] @ B[K,N] (+ bias).  M,N,K multiples of 128/128/16.
// Block tile 128x128, BK=16, 256 threads, 8x8 per thread (split 4+4 pattern).
// ---------------------------------------------------------------------------
template<int ADD_BIAS>
__global__ void __launch_bounds__(256)
sgemm_kernel(const float* __restrict__ A, const float* __restrict__ B,
             const float* __restrict__ bias, float* __restrict__ C,
             int M, int N, int K)
{
    __shared__ float As[16][128];   // stored transposed: As[k][m]
    __shared__ float Bs[16][128];   // Bs[k][n]

    const int tid  = threadIdx.x;
    const int tx   = tid & 15;
    const int ty   = tid >> 4;
    const int rowA = blockIdx.y * 128;
    const int colB = blockIdx.x * 128;

    float acc[8][8];
#pragma unroll
    for (int i = 0; i < 8; ++i)
#pragma unroll
        for (int j = 0; j < 8; ++j) acc[i][j] = 0.f;

    for (int k0 = 0; k0 < K; k0 += 16) {
#pragma unroll
        for (int u = 0; u < 2; ++u) {
            int f = tid * 2 + u;                      // 0..511
            // A tile: 128 rows x 16 cols -> 4 float4 per row
            int r  = f >> 2, c4 = f & 3;
            float4 a4 = *(const float4*)(A + (size_t)(rowA + r) * K + k0 + c4 * 4);
            As[c4 * 4 + 0][r] = a4.x;
            As[c4 * 4 + 1][r] = a4.y;
            As[c4 * 4 + 2][r] = a4.z;
            As[c4 * 4 + 3][r] = a4.w;
            // B tile: 16 rows x 128 cols -> 32 float4 per row
            int rb = f >> 5, cb4 = f & 31;
            float4 b4 = *(const float4*)(B + (size_t)(k0 + rb) * N + colB + cb4 * 4);
            *(float4*)&Bs[rb][cb4 * 4] = b4;
        }
        __syncthreads();

#pragma unroll
        for (int kk = 0; kk < 16; ++kk) {
            float4 a0 = *(const float4*)&As[kk][ty * 4];
            float4 a1 = *(const float4*)&As[kk][64 + ty * 4];
            float4 b0 = *(const float4*)&Bs[kk][tx * 4];
            float4 b1 = *(const float4*)&Bs[kk][64 + tx * 4];
            float av[8] = {a0.x, a0.y, a0.z, a0.w, a1.x, a1.y, a1.z, a1.w};
            float bv[8] = {b0.x, b0.y, b0.z, b0.w, b1.x, b1.y, b1.z, b1.w};
#pragma unroll
            for (int i = 0; i < 8; ++i)
#pragma unroll
                for (int j = 0; j < 8; ++j)
                    acc[i][j] += av[i] * bv[j];
        }
        __syncthreads();
    }

#pragma unroll
    for (int ih = 0; ih < 2; ++ih)
#pragma unroll
        for (int ii = 0; ii < 4; ++ii) {
            int r = rowA + ih * 64 + ty * 4 + ii;
#pragma unroll
            for (int jh = 0; jh < 2; ++jh) {
                int c = colB + jh * 64 + tx * 4;
                float4 o;
                o.x = acc[ih * 4 + ii][jh * 4 + 0];
                o.y = acc[ih * 4 + ii][jh * 4 + 1];
                o.z = acc[ih * 4 + ii][jh * 4 + 2];
                o.w = acc[ih * 4 + ii][jh * 4 + 3];
                if (ADD_BIAS) {
                    float4 bb = *(const float4*)(bias + c);
                    o.x += bb.x; o.y += bb.y; o.z += bb.z; o.w += bb.w;
                }
                *(float4*)(C + (size_t)r * N + c) = o;
            }
        }
}

// ---------------------------------------------------------------------------
// Flash attention (fp32, causal). One block = 64 queries x one (b,h).
// 256 threads: thread (i = tid/4, sub = tid%4) owns S-row i, cols sub*16..+15
// and O-row i, dims sub*16..+15.
// smem: QsT[k][i] (stride 68), KsT[k][j] (stride 68, reused as P[i][j]),
//       Vs[j][d] (stride 64).  Total 51200 B -> needs dynamic smem attr.
// ---------------------------------------------------------------------------
#define QK_STRIDE 68
#define SM_FLOATS (2 * 64 * QK_STRIDE + 64 * 64)

__global__ void __launch_bounds__(256)
flash_attn_kernel(const float* __restrict__ q, const float* __restrict__ k,
                  const float* __restrict__ v, float* __restrict__ ctx)
{
    extern __shared__ float sm[];
    float* QsT = sm;                       // 64 x 68
    float* KsT = sm + 64 * QK_STRIDE;      // 64 x 68 (reused for P)
    float* Vs  = sm + 2 * 64 * QK_STRIDE;  // 64 x 64

    // reverse qt so the heaviest (most causal work) blocks launch first
    const int qt  = (int)gridDim.x - 1 - (int)blockIdx.x;   // 0..31
    const int bh  = blockIdx.y;                             // 0..31
    const int b   = bh >> 4;
    const int h   = bh & 15;
    const int q0  = qt * 64;
    const int tid = threadIdx.x;
    const int i   = tid >> 2;        // query row in tile
    const int sub = tid & 3;
    const int j0  = sub * 16;        // S-col group / O-dim group

    // ---- load Q tile transposed ----
    const float* qbase = q + ((size_t)b * SEQ + q0) * DMODEL + h * HDIM;
    for (int it = tid; it < 64 * 16; it += 256) {
        int row = it >> 4, c4 = it & 15;
        float4 t4 = *(const float4*)(qbase + (size_t)row * DMODEL + c4 * 4);
        QsT[(c4 * 4 + 0) * QK_STRIDE + row] = t4.x;
        QsT[(c4 * 4 + 1) * QK_STRIDE + row] = t4.y;
        QsT[(c4 * 4 + 2) * QK_STRIDE + row] = t4.z;
        QsT[(c4 * 4 + 3) * QK_STRIDE + row] = t4.w;
    }

    float m = -INFINITY, l = 0.f;
    float4 o0 = {0,0,0,0}, o1 = {0,0,0,0}, o2 = {0,0,0,0}, o3 = {0,0,0,0};
    const float scale = 0.125f;   // 1/sqrt(64)

    for (int kt = 0; kt <= qt; ++kt) {
        const int k0 = kt * 64;
        const float* kbase = k + ((size_t)b * SEQ + k0) * DMODEL + h * HDIM;
        const float* vbase = v + ((size_t)b * SEQ + k0) * DMODEL + h * HDIM;

        __syncthreads();  // previous iter's P/V reads complete before overwrite
        for (int it = tid; it < 64 * 16; it += 256) {
            int row = it >> 4, c4 = it & 15;
            float4 t4 = *(const float4*)(kbase + (size_t)row * DMODEL + c4 * 4);
            KsT[(c4 * 4 + 0) * QK_STRIDE + row] = t4.x;
            KsT[(c4 * 4 + 1) * QK_STRIDE + row] = t4.y;
            KsT[(c4 * 4 + 2) * QK_STRIDE + row] = t4.z;
            KsT[(c4 * 4 + 3) * QK_STRIDE + row] = t4.w;
            float4 v4 = *(const float4*)(vbase + (size_t)row * DMODEL + c4 * 4);
            *(float4*)&Vs[row * 64 + c4 * 4] = v4;
        }
        __syncthreads();

        // ---- S = Q K^T for my 16 columns ----
        float s[16];
#pragma unroll
        for (int jj = 0; jj < 16; ++jj) s[jj] = 0.f;
#pragma unroll 8
        for (int kk = 0; kk < 64; ++kk) {
            float qv = QsT[kk * QK_STRIDE + i];
            const float4* kr = (const float4*)&KsT[kk * QK_STRIDE + j0];
            float4 k0v = kr[0], k1v = kr[1], k2v = kr[2], k3v = kr[3];
            s[0]  += qv * k0v.x;  s[1]  += qv * k0v.y;  s[2]  += qv * k0v.z;  s[3]  += qv * k0v.w;
            s[4]  += qv * k1v.x;  s[5]  += qv * k1v.y;  s[6]  += qv * k1v.z;  s[7]  += qv * k1v.w;
            s[8]  += qv * k2v.x;  s[9]  += qv * k2v.y;  s[10] += qv * k2v.z;  s[11] += qv * k2v.w;
            s[12] += qv * k3v.x;  s[13] += qv * k3v.y;  s[14] += qv * k3v.z;  s[15] += qv * k3v.w;
        }

        const bool diag = (kt == qt);
        float tm = -INFINITY;
#pragma unroll
        for (int jj = 0; jj < 16; ++jj) {
            float sv = s[jj] * scale;
            if (diag && (j0 + jj) > i) sv = -INFINITY;
            s[jj] = sv;
            tm = fmaxf(tm, sv);
        }
        // quad reduce max (the 4 threads of a row are consecutive lanes)
        tm = fmaxf(tm, __shfl_xor_sync(0xffffffffu, tm, 1));
        tm = fmaxf(tm, __shfl_xor_sync(0xffffffffu, tm, 2));

        float mn    = fmaxf(m, tm);
        float alpha = __expf(m - mn);   // first tile: exp(-inf - finite) = 0
        float rs = 0.f;
#pragma unroll
        for (int jj = 0; jj < 16; ++jj) {
            float p = __expf(s[jj] - mn);
            s[jj] = p;
            rs += p;
        }
        rs += __shfl_xor_sync(0xffffffffu, rs, 1);
        rs += __shfl_xor_sync(0xffffffffu, rs, 2);

        l = l * alpha + rs;
        m = mn;
        o0.x *= alpha; o0.y *= alpha; o0.z *= alpha; o0.w *= alpha;
        o1.x *= alpha; o1.y *= alpha; o1.z *= alpha; o1.w *= alpha;
        o2.x *= alpha; o2.y *= alpha; o2.z *= alpha; o2.w *= alpha;
        o3.x *= alpha; o3.y *= alpha; o3.z *= alpha; o3.w *= alpha;

        // ---- P overwrites KsT (all S reads finished after the barrier) ----
        __syncthreads();
        float* Ps = KsT;
        *(float4*)&Ps[i * QK_STRIDE + j0 + 0]  = make_float4(s[0],  s[1],  s[2],  s[3]);
        *(float4*)&Ps[i * QK_STRIDE + j0 + 4]  = make_float4(s[4],  s[5],  s[6],  s[7]);
        *(float4*)&Ps[i * QK_STRIDE + j0 + 8]  = make_float4(s[8],  s[9],  s[10], s[11]);
        *(float4*)&Ps[i * QK_STRIDE + j0 + 12] = make_float4(s[12], s[13], s[14], s[15]);
        __syncwarp();   // row i's P is produced & consumed by the same quad

        // ---- O += P @ V ----
#pragma unroll 8
        for (int j = 0; j < 64; ++j) {
            float pv = Ps[i * QK_STRIDE + j];
            const float4* vr = (const float4*)&Vs[j * 64 + j0];
            float4 v0 = vr[0], v1 = vr[1], v2 = vr[2], v3 = vr[3];
            o0.x += pv * v0.x; o0.y += pv * v0.y; o0.z += pv * v0.z; o0.w += pv * v0.w;
            o1.x += pv * v1.x; o1.y += pv * v1.y; o1.z += pv * v1.z; o1.w += pv * v1.w;
            o2.x += pv * v2.x; o2.y += pv * v2.y; o2.z += pv * v2.z; o2.w += pv * v2.w;
            o3.x += pv * v3.x; o3.y += pv * v3.y; o3.z += pv * v3.z; o3.w += pv * v3.w;
        }
    }

    const float inv = 1.f / l;
    float* obase = ctx + ((size_t)b * SEQ + q0 + i) * DMODEL + h * HDIM + j0;
    o0.x *= inv; o0.y *= inv; o0.z *= inv; o0.w *= inv;
    o1.x *= inv; o1.y *= inv; o1.z *= inv; o1.w *= inv;
    o2.x *= inv; o2.y *= inv; o2.z *= inv; o2.w *= inv;
    o3.x *= inv; o3.y *= inv; o3.z *= inv; o3.w *= inv;
    *(float4*)(obase + 0)  = o0;
    *(float4*)(obase + 4)  = o1;
    *(float4*)(obase + 8)  = o2;
    *(float4*)(obase + 12) = o3;
}

// ---------------------------------------------------------------------------
// Launch: 3x QKV GEMM -> flash attention -> output GEMM + bias.
// Graph-capturable: kernel launches only (+ immediate attribute/symbol APIs).
// ---------------------------------------------------------------------------
extern "C" void kernel_launch(void* const* d_in, const int* in_sizes, int n_in,
                              void* d_out, int out_size)
{
    const float* x  = (const float*)d_in[0];
    const float* Wq = (const float*)d_in[1];
    const float* Wk = (const float*)d_in[2];
    const float* Wv = (const float*)d_in[3];
    const float* Wo = (const float*)d_in[4];
    const float* bo = (const float*)d_in[5];
    float* out = (float*)d_out;

    float *pq, *pk, *pv, *pc;
    cudaGetSymbolAddress((void**)&pq, g_q);
    cudaGetSymbolAddress((void**)&pk, g_k);
    cudaGetSymbolAddress((void**)&pv, g_v);
    cudaGetSymbolAddress((void**)&pc, g_ctx);

    dim3 gg(DMODEL / 128, MTOT / 128);   // (8, 32)
    sgemm_kernel<0><<<gg, 256>>>(x, Wq, nullptr, pq, MTOT, DMODEL, DMODEL);
    sgemm_kernel<0><<<gg, 256>>>(x, Wk, nullptr, pk, MTOT, DMODEL, DMODEL);
    sgemm_kernel<0><<<gg, 256>>>(x, Wv, nullptr, pv, MTOT, DMODEL, DMODEL);

    size_t smem = SM_FLOATS * sizeof(float);   // 51200 B > 48KB default
    cudaFuncSetAttribute(flash_attn_kernel,
                         cudaFuncAttributeMaxDynamicSharedMemorySize, (int)smem);
    flash_attn_kernel<<<dim3(SEQ / 64, BATCH * NHEAD), 256, smem>>>(pq, pk, pv, pc);

    sgemm_kernel<1><<<gg, 256>>>(pc, Wo, bo, out, MTOT, DMODEL, DMODEL);
}

// round 5
// speedup vs baseline: 1.1831x; 1.1831x over previous
#include <cuda_runtime.h>
#include <math.h>
#include <stdint.h>

// ---------------------------------------------------------------------------
// MHA: x[2,2048,1024], 16 heads x 64, causal, fp32 I/O.
// R4: projections via mma.sync tf32 (m16n8k8) warp MMA; flash attention fp32.
// (tcgen05 is unavailable: harness PTX target is sm_103 without the 'a' suffix.)
// ---------------------------------------------------------------------------
#define BATCH   2
#define SEQ     2048
#define DMODEL  1024
#define NHEAD   16
#define HDIM    64
#define MTOT    (BATCH * SEQ)          // 4096 rows

// Scratch (device globals: no allocations allowed)
__device__ float g_q[MTOT * DMODEL];
__device__ float g_k[MTOT * DMODEL];
__device__ float g_v[MTOT * DMODEL];
__device__ float g_ctx[MTOT * DMODEL];
__device__ float g_wT[4][DMODEL * DMODEL];   // transposed + tf32-rounded weights

__device__ __forceinline__ float to_tf32(float x) {
    uint32_t i = __float_as_uint(x), o;
    asm("cvt.rna.tf32.f32 %0, %1;" : "=r"(o) : "r"(i));
    return __uint_as_float(o);
}

// ---------------------------------------------------------------------------
// Weight transpose + tf32 rounding:  D[n*K + k] = tf32(S[k*N + n]),  1024x1024
// ---------------------------------------------------------------------------
__global__ void __launch_bounds__(256)
transpose_round_kernel(const float* __restrict__ S, float* __restrict__ D)
{
    __shared__ float t[32][33];
    const int bx = blockIdx.x * 32, by = blockIdx.y * 32;
    const int txx = threadIdx.x;
    for (int j = threadIdx.y; j < 32; j += 8)
        t[j][txx] = S[(size_t)(by + j) * DMODEL + bx + txx];
    __syncthreads();
    for (int j = threadIdx.y; j < 32; j += 8)
        D[(size_t)(bx + j) * DMODEL + by + txx] = to_tf32(t[txx][j]);
}

// ---------------------------------------------------------------------------
// tf32 warp-MMA GEMM:  C[M,N] = A[M,K] @ BT[N,K]^T  (+ bias)
// Block 128x128, BK=32, 8 warps (4x2), warp tile 32x64.
// mma.sync.aligned.m16n8k8.row.col.f32.tf32.tf32.f32
// Smem padded to stride 36 floats -> all fragment LDS are conflict-free.
// ---------------------------------------------------------------------------
#define AS_STRIDE 36

#define MMA_TF32(c0, c1, c2, c3, a0, a1, a2, a3, b0, b1)                     \
    asm volatile("mma.sync.aligned.m16n8k8.row.col.f32.tf32.tf32.f32 "       \
                 "{%0,%1,%2,%3}, {%4,%5,%6,%7}, {%8,%9}, {%0,%1,%2,%3};"     \
                 : "+f"(c0), "+f"(c1), "+f"(c2), "+f"(c3)                    \
                 : "r"(a0), "r"(a1), "r"(a2), "r"(a3), "r"(b0), "r"(b1))

template<int ADD_BIAS>
__global__ void __launch_bounds__(256)
tf32_gemm_kernel(const float* __restrict__ A, const float* __restrict__ BT,
                 const float* __restrict__ bias, float* __restrict__ C)
{
    __shared__ float As[128 * AS_STRIDE];
    __shared__ float Bs[128 * AS_STRIDE];

    const int tid  = threadIdx.x;
    const int wid  = tid >> 5;
    const int lane = tid & 31;
    const int wm   = wid & 3;          // warp row block (32 rows)
    const int wn   = wid >> 2;         // warp col block (64 cols)
    const int gid  = lane >> 2;        // group id 0..7
    const int tg   = lane & 3;         // thread-in-group 0..3
    const int rowA = blockIdx.y * 128;
    const int colB = blockIdx.x * 128;

    float c[2][8][4];
#pragma unroll
    for (int mt = 0; mt < 2; ++mt)
#pragma unroll
        for (int nt = 0; nt < 8; ++nt)
#pragma unroll
            for (int r = 0; r < 4; ++r) c[mt][nt][r] = 0.f;

    for (int k0 = 0; k0 < DMODEL; k0 += 32) {
        // ---- load tiles: 128 rows x 32 cols each, 4 float4 per thread ----
#pragma unroll
        for (int i = 0; i < 4; ++i) {
            int idx = tid + i * 256;       // 0..1023
            int r = idx >> 3, c4 = idx & 7;
            float4 va = *(const float4*)(A + (size_t)(rowA + r) * DMODEL + k0 + c4 * 4);
            va.x = to_tf32(va.x); va.y = to_tf32(va.y);
            va.z = to_tf32(va.z); va.w = to_tf32(va.w);
            *(float4*)&As[r * AS_STRIDE + c4 * 4] = va;
            float4 vb = *(const float4*)(BT + (size_t)(colB + r) * DMODEL + k0 + c4 * 4);
            *(float4*)&Bs[r * AS_STRIDE + c4 * 4] = vb;
        }
        __syncthreads();

#pragma unroll
        for (int ks = 0; ks < 4; ++ks) {
            const int kb = ks * 8;
            uint32_t a[2][4], b[8][2];
#pragma unroll
            for (int mt = 0; mt < 2; ++mt) {
                const int mb = wm * 32 + mt * 16;
                a[mt][0] = __float_as_uint(As[(mb + gid    ) * AS_STRIDE + kb + tg    ]);
                a[mt][1] = __float_as_uint(As[(mb + gid + 8) * AS_STRIDE + kb + tg    ]);
                a[mt][2] = __float_as_uint(As[(mb + gid    ) * AS_STRIDE + kb + tg + 4]);
                a[mt][3] = __float_as_uint(As[(mb + gid + 8) * AS_STRIDE + kb + tg + 4]);
            }
#pragma unroll
            for (int nt = 0; nt < 8; ++nt) {
                const int nb = wn * 64 + nt * 8;
                b[nt][0] = __float_as_uint(Bs[(nb + gid) * AS_STRIDE + kb + tg    ]);
                b[nt][1] = __float_as_uint(Bs[(nb + gid) * AS_STRIDE + kb + tg + 4]);
            }
#pragma unroll
            for (int mt = 0; mt < 2; ++mt)
#pragma unroll
                for (int nt = 0; nt < 8; ++nt)
                    MMA_TF32(c[mt][nt][0], c[mt][nt][1], c[mt][nt][2], c[mt][nt][3],
                             a[mt][0], a[mt][1], a[mt][2], a[mt][3],
                             b[nt][0], b[nt][1]);
        }
        __syncthreads();
    }

    // ---- epilogue: c0/c1 -> (row, 2tg..2tg+1), c2/c3 -> (row+8, ...) ----
#pragma unroll
    for (int mt = 0; mt < 2; ++mt) {
        const int r0 = rowA + wm * 32 + mt * 16 + gid;
#pragma unroll
        for (int nt = 0; nt < 8; ++nt) {
            const int col = colB + wn * 64 + nt * 8 + tg * 2;
            float bx = 0.f, by = 0.f;
            if (ADD_BIAS) { bx = bias[col]; by = bias[col + 1]; }
            float2 lo = make_float2(c[mt][nt][0] + bx, c[mt][nt][1] + by);
            float2 hi = make_float2(c[mt][nt][2] + bx, c[mt][nt][3] + by);
            *(float2*)(C + (size_t)r0 * DMODEL + col)       = lo;
            *(float2*)(C + (size_t)(r0 + 8) * DMODEL + col) = hi;
        }
    }
}

// ---------------------------------------------------------------------------
// Flash attention (fp32, causal) — unchanged (validated, rel_err 7e-7 path).
// ---------------------------------------------------------------------------
#define QK_STRIDE 68
#define SM_FLOATS (2 * 64 * QK_STRIDE + 64 * 64)

__global__ void __launch_bounds__(256)
flash_attn_kernel(const float* __restrict__ q, const float* __restrict__ k,
                  const float* __restrict__ v, float* __restrict__ ctx)
{
    extern __shared__ float smf[];
    float* QsT = smf;
    float* KsT = smf + 64 * QK_STRIDE;
    float* Vs  = smf + 2 * 64 * QK_STRIDE;

    const int qt  = (int)gridDim.x - 1 - (int)blockIdx.x;
    const int bh  = blockIdx.y;
    const int b   = bh >> 4;
    const int h   = bh & 15;
    const int q0  = qt * 64;
    const int tid = threadIdx.x;
    const int i   = tid >> 2;
    const int sub = tid & 3;
    const int j0  = sub * 16;

    const float* qbase = q + ((size_t)b * SEQ + q0) * DMODEL + h * HDIM;
    for (int it = tid; it < 64 * 16; it += 256) {
        int row = it >> 4, c4 = it & 15;
        float4 t4 = *(const float4*)(qbase + (size_t)row * DMODEL + c4 * 4);
        QsT[(c4 * 4 + 0) * QK_STRIDE + row] = t4.x;
        QsT[(c4 * 4 + 1) * QK_STRIDE + row] = t4.y;
        QsT[(c4 * 4 + 2) * QK_STRIDE + row] = t4.z;
        QsT[(c4 * 4 + 3) * QK_STRIDE + row] = t4.w;
    }

    float m = -INFINITY, l = 0.f;
    float4 o0 = {0,0,0,0}, o1 = {0,0,0,0}, o2 = {0,0,0,0}, o3 = {0,0,0,0};
    const float scale = 0.125f;

    for (int kt = 0; kt <= qt; ++kt) {
        const int k0 = kt * 64;
        const float* kbase = k + ((size_t)b * SEQ + k0) * DMODEL + h * HDIM;
        const float* vbase = v + ((size_t)b * SEQ + k0) * DMODEL + h * HDIM;

        __syncthreads();
        for (int it = tid; it < 64 * 16; it += 256) {
            int row = it >> 4, c4 = it & 15;
            float4 t4 = *(const float4*)(kbase + (size_t)row * DMODEL + c4 * 4);
            KsT[(c4 * 4 + 0) * QK_STRIDE + row] = t4.x;
            KsT[(c4 * 4 + 1) * QK_STRIDE + row] = t4.y;
            KsT[(c4 * 4 + 2) * QK_STRIDE + row] = t4.z;
            KsT[(c4 * 4 + 3) * QK_STRIDE + row] = t4.w;
            float4 v4 = *(const float4*)(vbase + (size_t)row * DMODEL + c4 * 4);
            *(float4*)&Vs[row * 64 + c4 * 4] = v4;
        }
        __syncthreads();

        float s[16];
#pragma unroll
        for (int jj = 0; jj < 16; ++jj) s[jj] = 0.f;
#pragma unroll 8
        for (int kk = 0; kk < 64; ++kk) {
            float qv = QsT[kk * QK_STRIDE + i];
            const float4* kr = (const float4*)&KsT[kk * QK_STRIDE + j0];
            float4 k0v = kr[0], k1v = kr[1], k2v = kr[2], k3v = kr[3];
            s[0]  += qv * k0v.x;  s[1]  += qv * k0v.y;  s[2]  += qv * k0v.z;  s[3]  += qv * k0v.w;
            s[4]  += qv * k1v.x;  s[5]  += qv * k1v.y;  s[6]  += qv * k1v.z;  s[7]  += qv * k1v.w;
            s[8]  += qv * k2v.x;  s[9]  += qv * k2v.y;  s[10] += qv * k2v.z;  s[11] += qv * k2v.w;
            s[12] += qv * k3v.x;  s[13] += qv * k3v.y;  s[14] += qv * k3v.z;  s[15] += qv * k3v.w;
        }

        const bool diag = (kt == qt);
        float tm = -INFINITY;
#pragma unroll
        for (int jj = 0; jj < 16; ++jj) {
            float sv = s[jj] * scale;
            if (diag && (j0 + jj) > i) sv = -INFINITY;
            s[jj] = sv;
            tm = fmaxf(tm, sv);
        }
        tm = fmaxf(tm, __shfl_xor_sync(0xffffffffu, tm, 1));
        tm = fmaxf(tm, __shfl_xor_sync(0xffffffffu, tm, 2));

        float mn    = fmaxf(m, tm);
        float alpha = __expf(m - mn);
        float rs = 0.f;
#pragma unroll
        for (int jj = 0; jj < 16; ++jj) {
            float p = __expf(s[jj] - mn);
            s[jj] = p;
            rs += p;
        }
        rs += __shfl_xor_sync(0xffffffffu, rs, 1);
        rs += __shfl_xor_sync(0xffffffffu, rs, 2);

        l = l * alpha + rs;
        m = mn;
        o0.x *= alpha; o0.y *= alpha; o0.z *= alpha; o0.w *= alpha;
        o1.x *= alpha; o1.y *= alpha; o1.z *= alpha; o1.w *= alpha;
        o2.x *= alpha; o2.y *= alpha; o2.z *= alpha; o2.w *= alpha;
        o3.x *= alpha; o3.y *= alpha; o3.z *= alpha; o3.w *= alpha;

        __syncthreads();
        float* Ps = KsT;
        *(float4*)&Ps[i * QK_STRIDE + j0 + 0]  = make_float4(s[0],  s[1],  s[2],  s[3]);
        *(float4*)&Ps[i * QK_STRIDE + j0 + 4]  = make_float4(s[4],  s[5],  s[6],  s[7]);
        *(float4*)&Ps[i * QK_STRIDE + j0 + 8]  = make_float4(s[8],  s[9],  s[10], s[11]);
        *(float4*)&Ps[i * QK_STRIDE + j0 + 12] = make_float4(s[12], s[13], s[14], s[15]);
        __syncwarp();

#pragma unroll 8
        for (int j = 0; j < 64; ++j) {
            float pv = Ps[i * QK_STRIDE + j];
            const float4* vr = (const float4*)&Vs[j * 64 + j0];
            float4 v0 = vr[0], v1 = vr[1], v2 = vr[2], v3 = vr[3];
            o0.x += pv * v0.x; o0.y += pv * v0.y; o0.z += pv * v0.z; o0.w += pv * v0.w;
            o1.x += pv * v1.x; o1.y += pv * v1.y; o1.z += pv * v1.z; o1.w += pv * v1.w;
            o2.x += pv * v2.x; o2.y += pv * v2.y; o2.z += pv * v2.z; o2.w += pv * v2.w;
            o3.x += pv * v3.x; o3.y += pv * v3.y; o3.z += pv * v3.z; o3.w += pv * v3.w;
        }
    }

    const float inv = 1.f / l;
    float* obase = ctx + ((size_t)b * SEQ + q0 + i) * DMODEL + h * HDIM + j0;
    o0.x *= inv; o0.y *= inv; o0.z *= inv; o0.w *= inv;
    o1.x *= inv; o1.y *= inv; o1.z *= inv; o1.w *= inv;
    o2.x *= inv; o2.y *= inv; o2.z *= inv; o2.w *= inv;
    o3.x *= inv; o3.y *= inv; o3.z *= inv; o3.w *= inv;
    *(float4*)(obase + 0)  = o0;
    *(float4*)(obase + 4)  = o1;
    *(float4*)(obase + 8)  = o2;
    *(float4*)(obase + 12) = o3;
}

// ---------------------------------------------------------------------------
// Launch: 4x transpose -> 3x tf32 GEMM -> flash -> tf32 GEMM + bias
// ---------------------------------------------------------------------------
extern "C" void kernel_launch(void* const* d_in, const int* in_sizes, int n_in,
                              void* d_out, int out_size)
{
    const float* x  = (const float*)d_in[0];
    const float* Wq = (const float*)d_in[1];
    const float* Wk = (const float*)d_in[2];
    const float* Wv = (const float*)d_in[3];
    const float* Wo = (const float*)d_in[4];
    const float* bo = (const float*)d_in[5];
    float* out = (float*)d_out;

    float *pq, *pk, *pv, *pc, *pw;
    cudaGetSymbolAddress((void**)&pq, g_q);
    cudaGetSymbolAddress((void**)&pk, g_k);
    cudaGetSymbolAddress((void**)&pv, g_v);
    cudaGetSymbolAddress((void**)&pc, g_ctx);
    cudaGetSymbolAddress((void**)&pw, g_wT);
    float* wT[4] = { pw, pw + DMODEL * DMODEL, pw + 2 * DMODEL * DMODEL,
                     pw + 3 * DMODEL * DMODEL };

    dim3 tb(32, 8), tg(DMODEL / 32, DMODEL / 32);
    transpose_round_kernel<<<tg, tb>>>(Wq, wT[0]);
    transpose_round_kernel<<<tg, tb>>>(Wk, wT[1]);
    transpose_round_kernel<<<tg, tb>>>(Wv, wT[2]);
    transpose_round_kernel<<<tg, tb>>>(Wo, wT[3]);

    dim3 gg(DMODEL / 128, MTOT / 128);   // (8, 32)
    tf32_gemm_kernel<0><<<gg, 256>>>(x, wT[0], nullptr, pq);
    tf32_gemm_kernel<0><<<gg, 256>>>(x, wT[1], nullptr, pk);
    tf32_gemm_kernel<0><<<gg, 256>>>(x, wT[2], nullptr, pv);

    size_t smem = SM_FLOATS * sizeof(float);
    cudaFuncSetAttribute(flash_attn_kernel,
                         cudaFuncAttributeMaxDynamicSharedMemorySize, (int)smem);
    flash_attn_kernel<<<dim3(SEQ / 64, BATCH * NHEAD), 256, smem>>>(pq, pk, pv, pc);

    tf32_gemm_kernel<1><<<gg, 256>>>(pc, wT[3], bo, out);
}

// round 7
// speedup vs baseline: 6.2960x; 5.3215x over previous
#include <cuda_runtime.h>
#include <math.h>
#include <stdint.h>

// ---------------------------------------------------------------------------
// MHA: x[2,2048,1024], 16 heads x 64, causal, fp32 I/O.
// R6: R5 design (mma.sync tf32 everywhere) with the Ps smem-overflow fixed:
//     Ps now has 128 rows (one per CTA-local query row), was 64.
// ---------------------------------------------------------------------------
#define BATCH   2
#define SEQ     2048
#define DMODEL  1024
#define NHEAD   16
#define HDIM    64
#define MTOT    (BATCH * SEQ)          // 4096 rows

__device__ float g_q[MTOT * DMODEL];
__device__ float g_k[MTOT * DMODEL];
__device__ float g_v[MTOT * DMODEL];
__device__ float g_ctx[MTOT * DMODEL];
__device__ float g_wT[4][DMODEL * DMODEL];   // transposed + tf32-rounded weights

__device__ __forceinline__ float to_tf32(float x) {
    uint32_t i = __float_as_uint(x), o;
    asm("cvt.rna.tf32.f32 %0, %1;" : "=r"(o) : "r"(i));
    return __uint_as_float(o);
}

#define MMA_TF32(c0, c1, c2, c3, a0, a1, a2, a3, b0, b1)                     \
    asm volatile("mma.sync.aligned.m16n8k8.row.col.f32.tf32.tf32.f32 "       \
                 "{%0,%1,%2,%3}, {%4,%5,%6,%7}, {%8,%9}, {%0,%1,%2,%3};"     \
                 : "+f"(c0), "+f"(c1), "+f"(c2), "+f"(c3)                    \
                 : "r"(a0), "r"(a1), "r"(a2), "r"(a3), "r"(b0), "r"(b1))

// ---------------------------------------------------------------------------
// Weight transpose + tf32 rounding:  D[n*K + k] = tf32(S[k*N + n])
// ---------------------------------------------------------------------------
__global__ void __launch_bounds__(256)
transpose_round_kernel(const float* __restrict__ S, float* __restrict__ D)
{
    __shared__ float t[32][33];
    const int bx = blockIdx.x * 32, by = blockIdx.y * 32;
    const int txx = threadIdx.x;
    for (int j = threadIdx.y; j < 32; j += 8)
        t[j][txx] = S[(size_t)(by + j) * DMODEL + bx + txx];
    __syncthreads();
    for (int j = threadIdx.y; j < 32; j += 8)
        D[(size_t)(bx + j) * DMODEL + by + txx] = to_tf32(t[txx][j]);
}

// ---------------------------------------------------------------------------
// tf32 warp-MMA GEMM: C = A[M,K] @ BT[N,K]^T (+bias). Block 128x128, BK=32.
// FUSED=1: grid.x = 24, routes output to C0/C1/C2 (QKV in one launch).
// ---------------------------------------------------------------------------
#define AS_STRIDE 36

template<int FUSED, int ADD_BIAS>
__global__ void __launch_bounds__(256)
tf32_gemm_kernel(const float* __restrict__ A, const float* __restrict__ BT0,
                 const float* __restrict__ bias,
                 float* __restrict__ C0, float* __restrict__ C1,
                 float* __restrict__ C2)
{
    __shared__ float As[128 * AS_STRIDE];
    __shared__ float Bs[128 * AS_STRIDE];

    const int tid  = threadIdx.x;
    const int wid  = tid >> 5;
    const int lane = tid & 31;
    const int wm   = wid & 3;
    const int wn   = wid >> 2;
    const int gid  = lane >> 2;
    const int tg   = lane & 3;
    const int rowA = blockIdx.y * 128;

    int which = 0, bx = blockIdx.x;
    if (FUSED) { which = blockIdx.x >> 3; bx = blockIdx.x & 7; }
    const int colB = bx * 128;
    const float* BT = BT0 + (size_t)which * DMODEL * DMODEL;
    float* C = (which == 0) ? C0 : (which == 1) ? C1 : C2;

    float c[2][8][4];
#pragma unroll
    for (int mt = 0; mt < 2; ++mt)
#pragma unroll
        for (int nt = 0; nt < 8; ++nt)
#pragma unroll
            for (int r = 0; r < 4; ++r) c[mt][nt][r] = 0.f;

    for (int k0 = 0; k0 < DMODEL; k0 += 32) {
#pragma unroll
        for (int i = 0; i < 4; ++i) {
            int idx = tid + i * 256;
            int r = idx >> 3, c4 = idx & 7;
            float4 va = *(const float4*)(A + (size_t)(rowA + r) * DMODEL + k0 + c4 * 4);
            va.x = to_tf32(va.x); va.y = to_tf32(va.y);
            va.z = to_tf32(va.z); va.w = to_tf32(va.w);
            *(float4*)&As[r * AS_STRIDE + c4 * 4] = va;
            float4 vb = *(const float4*)(BT + (size_t)(colB + r) * DMODEL + k0 + c4 * 4);
            *(float4*)&Bs[r * AS_STRIDE + c4 * 4] = vb;
        }
        __syncthreads();

#pragma unroll
        for (int ks = 0; ks < 4; ++ks) {
            const int kb = ks * 8;
            uint32_t a[2][4], b[8][2];
#pragma unroll
            for (int mt = 0; mt < 2; ++mt) {
                const int mb = wm * 32 + mt * 16;
                a[mt][0] = __float_as_uint(As[(mb + gid    ) * AS_STRIDE + kb + tg    ]);
                a[mt][1] = __float_as_uint(As[(mb + gid + 8) * AS_STRIDE + kb + tg    ]);
                a[mt][2] = __float_as_uint(As[(mb + gid    ) * AS_STRIDE + kb + tg + 4]);
                a[mt][3] = __float_as_uint(As[(mb + gid + 8) * AS_STRIDE + kb + tg + 4]);
            }
#pragma unroll
            for (int nt = 0; nt < 8; ++nt) {
                const int nb = wn * 64 + nt * 8;
                b[nt][0] = __float_as_uint(Bs[(nb + gid) * AS_STRIDE + kb + tg    ]);
                b[nt][1] = __float_as_uint(Bs[(nb + gid) * AS_STRIDE + kb + tg + 4]);
            }
#pragma unroll
            for (int mt = 0; mt < 2; ++mt)
#pragma unroll
                for (int nt = 0; nt < 8; ++nt)
                    MMA_TF32(c[mt][nt][0], c[mt][nt][1], c[mt][nt][2], c[mt][nt][3],
                             a[mt][0], a[mt][1], a[mt][2], a[mt][3],
                             b[nt][0], b[nt][1]);
        }
        __syncthreads();
    }

#pragma unroll
    for (int mt = 0; mt < 2; ++mt) {
        const int r0 = rowA + wm * 32 + mt * 16 + gid;
#pragma unroll
        for (int nt = 0; nt < 8; ++nt) {
            const int col = colB + wn * 64 + nt * 8 + tg * 2;
            float bxv = 0.f, byv = 0.f;
            if (ADD_BIAS) { bxv = bias[col]; byv = bias[col + 1]; }
            float2 lo = make_float2(c[mt][nt][0] + bxv, c[mt][nt][1] + byv);
            float2 hi = make_float2(c[mt][nt][2] + bxv, c[mt][nt][3] + byv);
            *(float2*)(C + (size_t)r0 * DMODEL + col)       = lo;
            *(float2*)(C + (size_t)(r0 + 8) * DMODEL + col) = hi;
        }
    }
}

// ---------------------------------------------------------------------------
// Flash attention, tf32 mma. One CTA = 128 queries x one (b,h). 8 warps.
// Warp w owns query rows w*16..w*16+15.  Key tiles of 64.
// smem: Qs[128][68], Ks[64][68] ([key][dim] = B for S), VsT[64][68]
//       ([dim][key] = B for PV), Ps[128][68]  <-- 128 rows (R6 fix).
// ---------------------------------------------------------------------------
#define FS 68
#define F_QS   0
#define F_KS   (128 * FS)
#define F_VST  (F_KS  + 64 * FS)
#define F_PS   (F_VST + 64 * FS)
#define F_TOTAL ((128 + 64 + 64 + 128) * FS)   // floats; 104,448 B

__global__ void __launch_bounds__(256)
flash_mma_kernel(const float* __restrict__ q, const float* __restrict__ k,
                 const float* __restrict__ v, float* __restrict__ ctx)
{
    extern __shared__ float smf[];
    float* Qs  = smf + F_QS;
    float* Ks  = smf + F_KS;
    float* VsT = smf + F_VST;
    float* Ps  = smf + F_PS;

    const int qt  = (int)gridDim.x - 1 - (int)blockIdx.x;   // 0..15, heavy first
    const int bh  = blockIdx.y;
    const int b   = bh >> 4;
    const int h   = bh & 15;
    const int q0  = qt * 128;
    const int tid = threadIdx.x;
    const int wid = tid >> 5;
    const int lane = tid & 31;
    const int gid = lane >> 2;
    const int tg  = lane & 3;
    const int r0  = wid * 16 + gid;     // CTA-local query row (first half)
    const int r1  = r0 + 8;

    // ---- load Q tile [128 x 64], tf32-rounded ----
    const float* qbase = q + ((size_t)b * SEQ + q0) * DMODEL + h * HDIM;
    for (int it = tid; it < 128 * 16; it += 256) {
        int row = it >> 4, c4 = it & 15;
        float4 t4 = *(const float4*)(qbase + (size_t)row * DMODEL + c4 * 4);
        t4.x = to_tf32(t4.x); t4.y = to_tf32(t4.y);
        t4.z = to_tf32(t4.z); t4.w = to_tf32(t4.w);
        *(float4*)&Qs[row * FS + c4 * 4] = t4;
    }

    float m0 = -INFINITY, m1 = -INFINITY, l0 = 0.f, l1 = 0.f;
    float o[8][4];
#pragma unroll
    for (int nt = 0; nt < 8; ++nt)
#pragma unroll
        for (int r = 0; r < 4; ++r) o[nt][r] = 0.f;

    const int ktmax = 2 * qt + 1;
    for (int kt = 0; kt <= ktmax; ++kt) {
        const int k0 = kt * 64;
        const float* kbase = k + ((size_t)b * SEQ + k0) * DMODEL + h * HDIM;
        const float* vbase = v + ((size_t)b * SEQ + k0) * DMODEL + h * HDIM;

        __syncthreads();   // prev iter: Ks(S-mma)/VsT(PV) reads complete
        for (int it = tid; it < 64 * 16; it += 256) {
            int row = it >> 4, c4 = it & 15;
            float4 t4 = *(const float4*)(kbase + (size_t)row * DMODEL + c4 * 4);
            t4.x = to_tf32(t4.x); t4.y = to_tf32(t4.y);
            t4.z = to_tf32(t4.z); t4.w = to_tf32(t4.w);
            *(float4*)&Ks[row * FS + c4 * 4] = t4;
            float4 v4 = *(const float4*)(vbase + (size_t)row * DMODEL + c4 * 4);
            VsT[(c4 * 4 + 0) * FS + row] = to_tf32(v4.x);
            VsT[(c4 * 4 + 1) * FS + row] = to_tf32(v4.y);
            VsT[(c4 * 4 + 2) * FS + row] = to_tf32(v4.z);
            VsT[(c4 * 4 + 3) * FS + row] = to_tf32(v4.w);
        }
        __syncthreads();

        // ---- S = Q K^T : warp rows r0/r1, all 64 key cols ----
        float s[8][4];
#pragma unroll
        for (int nt = 0; nt < 8; ++nt)
#pragma unroll
            for (int r = 0; r < 4; ++r) s[nt][r] = 0.f;

        const float* qr0 = &Qs[r0 * FS];
        const float* qr1 = &Qs[r1 * FS];
#pragma unroll
        for (int ks = 0; ks < 8; ++ks) {
            const int kb = ks * 8;
            uint32_t a0 = __float_as_uint(qr0[kb + tg]);
            uint32_t a1 = __float_as_uint(qr1[kb + tg]);
            uint32_t a2 = __float_as_uint(qr0[kb + tg + 4]);
            uint32_t a3 = __float_as_uint(qr1[kb + tg + 4]);
#pragma unroll
            for (int nt = 0; nt < 8; ++nt) {
                uint32_t b0 = __float_as_uint(Ks[(nt * 8 + gid) * FS + kb + tg    ]);
                uint32_t b1 = __float_as_uint(Ks[(nt * 8 + gid) * FS + kb + tg + 4]);
                MMA_TF32(s[nt][0], s[nt][1], s[nt][2], s[nt][3],
                         a0, a1, a2, a3, b0, b1);
            }
        }

        // ---- scale + causal mask + row max ----
        const float scale = 0.125f;
        float tm0 = -INFINITY, tm1 = -INFINITY;
        const bool maskt = (kt >= 2 * qt);
        const int rel = k0 - q0;   // >= 0 when maskt
#pragma unroll
        for (int nt = 0; nt < 8; ++nt) {
            float s0 = s[nt][0] * scale, s1 = s[nt][1] * scale;
            float s2 = s[nt][2] * scale, s3 = s[nt][3] * scale;
            if (maskt) {
                int c0 = rel + nt * 8 + 2 * tg, c1 = c0 + 1;
                if (c0 > r0) s0 = -INFINITY;
                if (c1 > r0) s1 = -INFINITY;
                if (c0 > r1) s2 = -INFINITY;
                if (c1 > r1) s3 = -INFINITY;
            }
            s[nt][0] = s0; s[nt][1] = s1; s[nt][2] = s2; s[nt][3] = s3;
            tm0 = fmaxf(tm0, fmaxf(s0, s1));
            tm1 = fmaxf(tm1, fmaxf(s2, s3));
        }
        tm0 = fmaxf(tm0, __shfl_xor_sync(0xffffffffu, tm0, 1));
        tm0 = fmaxf(tm0, __shfl_xor_sync(0xffffffffu, tm0, 2));
        tm1 = fmaxf(tm1, __shfl_xor_sync(0xffffffffu, tm1, 1));
        tm1 = fmaxf(tm1, __shfl_xor_sync(0xffffffffu, tm1, 2));

        const float mn0 = fmaxf(m0, tm0), mn1 = fmaxf(m1, tm1);
        const float alpha0 = __expf(m0 - mn0), alpha1 = __expf(m1 - mn1);
        float rs0 = 0.f, rs1 = 0.f;
#pragma unroll
        for (int nt = 0; nt < 8; ++nt) {
            float p0 = __expf(s[nt][0] - mn0);
            float p1 = __expf(s[nt][1] - mn0);
            float p2 = __expf(s[nt][2] - mn1);
            float p3 = __expf(s[nt][3] - mn1);
            rs0 += p0 + p1;  rs1 += p2 + p3;
            const int cc = nt * 8 + 2 * tg;
            *(float2*)&Ps[r0 * FS + cc] = make_float2(to_tf32(p0), to_tf32(p1));
            *(float2*)&Ps[r1 * FS + cc] = make_float2(to_tf32(p2), to_tf32(p3));
        }
        rs0 += __shfl_xor_sync(0xffffffffu, rs0, 1);
        rs0 += __shfl_xor_sync(0xffffffffu, rs0, 2);
        rs1 += __shfl_xor_sync(0xffffffffu, rs1, 1);
        rs1 += __shfl_xor_sync(0xffffffffu, rs1, 2);

        l0 = l0 * alpha0 + rs0;  m0 = mn0;
        l1 = l1 * alpha1 + rs1;  m1 = mn1;
#pragma unroll
        for (int nt = 0; nt < 8; ++nt) {
            o[nt][0] *= alpha0; o[nt][1] *= alpha0;
            o[nt][2] *= alpha1; o[nt][3] *= alpha1;
        }
        __syncwarp();   // warp's own P rows fully written (cross-lane reads next)

        // ---- O += P V : A = Ps (warp's 16 rows), B = VsT[dim][key] ----
        const float* pr0 = &Ps[r0 * FS];
        const float* pr1 = &Ps[r1 * FS];
#pragma unroll
        for (int ks = 0; ks < 8; ++ks) {
            const int kb = ks * 8;
            uint32_t a0 = __float_as_uint(pr0[kb + tg]);
            uint32_t a1 = __float_as_uint(pr1[kb + tg]);
            uint32_t a2 = __float_as_uint(pr0[kb + tg + 4]);
            uint32_t a3 = __float_as_uint(pr1[kb + tg + 4]);
#pragma unroll
            for (int nt = 0; nt < 8; ++nt) {
                uint32_t b0 = __float_as_uint(VsT[(nt * 8 + gid) * FS + kb + tg    ]);
                uint32_t b1 = __float_as_uint(VsT[(nt * 8 + gid) * FS + kb + tg + 4]);
                MMA_TF32(o[nt][0], o[nt][1], o[nt][2], o[nt][3],
                         a0, a1, a2, a3, b0, b1);
            }
        }
    }

    // ---- write O ----
    const float inv0 = 1.f / l0, inv1 = 1.f / l1;
    float* ob0 = ctx + ((size_t)b * SEQ + q0 + r0) * DMODEL + h * HDIM;
    float* ob1 = ctx + ((size_t)b * SEQ + q0 + r1) * DMODEL + h * HDIM;
#pragma unroll
    for (int nt = 0; nt < 8; ++nt) {
        const int cc = nt * 8 + 2 * tg;
        *(float2*)(ob0 + cc) = make_float2(o[nt][0] * inv0, o[nt][1] * inv0);
        *(float2*)(ob1 + cc) = make_float2(o[nt][2] * inv1, o[nt][3] * inv1);
    }
}

// ---------------------------------------------------------------------------
// Launch: 4x transpose -> fused QKV GEMM -> flash(mma) -> out GEMM + bias
// ---------------------------------------------------------------------------
extern "C" void kernel_launch(void* const* d_in, const int* in_sizes, int n_in,
                              void* d_out, int out_size)
{
    const float* x  = (const float*)d_in[0];
    const float* Wq = (const float*)d_in[1];
    const float* Wk = (const float*)d_in[2];
    const float* Wv = (const float*)d_in[3];
    const float* Wo = (const float*)d_in[4];
    const float* bo = (const float*)d_in[5];
    float* out = (float*)d_out;

    float *pq, *pk, *pv, *pc, *pw;
    cudaGetSymbolAddress((void**)&pq, g_q);
    cudaGetSymbolAddress((void**)&pk, g_k);
    cudaGetSymbolAddress((void**)&pv, g_v);
    cudaGetSymbolAddress((void**)&pc, g_ctx);
    cudaGetSymbolAddress((void**)&pw, g_wT);

    dim3 tb(32, 8), tg(DMODEL / 32, DMODEL / 32);
    transpose_round_kernel<<<tg, tb>>>(Wq, pw);
    transpose_round_kernel<<<tg, tb>>>(Wk, pw + (size_t)DMODEL * DMODEL);
    transpose_round_kernel<<<tg, tb>>>(Wv, pw + 2 * (size_t)DMODEL * DMODEL);
    transpose_round_kernel<<<tg, tb>>>(Wo, pw + 3 * (size_t)DMODEL * DMODEL);

    // fused QKV: grid.x = 3 * 8
    tf32_gemm_kernel<1, 0><<<dim3(24, MTOT / 128), 256>>>(
        x, pw, nullptr, pq, pk, pv);

    size_t smem = F_TOTAL * sizeof(float);   // 104,448 B
    cudaFuncSetAttribute(flash_mma_kernel,
                         cudaFuncAttributeMaxDynamicSharedMemorySize, (int)smem);
    flash_mma_kernel<<<dim3(SEQ / 128, BATCH * NHEAD), 256, smem>>>(pq, pk, pv, pc);

    tf32_gemm_kernel<0, 1><<<dim3(8, MTOT / 128), 256>>>(
        pc, pw + 3 * (size_t)DMODEL * DMODEL, bo, out, nullptr, nullptr);
}